// round 4
// baseline (speedup 1.0000x reference)
#include <cuda_runtime.h>
#include <cstdint>

#define N_NODES 500000
#define N_EDGES 16000000

// Per-node gain: relu(v[n]) * type_params[type[n]].  2 MB, stays L2-hot.
__device__ float g_gain[N_NODES];

// ---------------------------------------------------------------------------
// Kernel A: node prep. g_gain[n] = relu(v)*tp[type], out[n] = -v + stim + Vrest
// ---------------------------------------------------------------------------
__global__ void node_prep(const float* __restrict__ voltage,
                          const float* __restrict__ stimulus,
                          const int*   __restrict__ ntype,      // int32 (JAX x64 off)
                          const float* __restrict__ v_rest,
                          const float* __restrict__ type_params,
                          float* __restrict__ out,
                          int n)
{
    int i = blockIdx.x * blockDim.x + threadIdx.x;
    if (i < n) {
        float v = voltage[i];
        float r = v > 0.0f ? v : 0.0f;
        int t = ntype[i];                 // values in [0,64)
        g_gain[i] = r * __ldg(&type_params[t]);
        out[i] = -v + stimulus[i] + v_rest[i];
    }
}

// ---------------------------------------------------------------------------
// Kernel B: edge scatter. 8 edges per thread.
// Front-batch all streaming loads (MLP=6), then 8 independent gathers,
// then 8 no-return atomics (RED.E.ADD.F32).
// ---------------------------------------------------------------------------
__global__ void __launch_bounds__(256) edge_scatter(
    const int4*   __restrict__ src4,   // edge_index row 0, int32 x4
    const int4*   __restrict__ dst4,   // edge_index row 1, int32 x4
    const float4* __restrict__ w4,
    float*        __restrict__ out,
    int n_groups)                      // N_EDGES / 8
{
    int i = blockIdx.x * blockDim.x + threadIdx.x;
    if (i >= n_groups) return;

    // 6 independent 128-bit streaming loads, evict-first (don't thrash
    // the L2-resident g_gain/out working set).
    int4   sa = __ldcs(&src4[2 * i]);
    int4   sb = __ldcs(&src4[2 * i + 1]);
    int4   da = __ldcs(&dst4[2 * i]);
    int4   db = __ldcs(&dst4[2 * i + 1]);
    float4 wa = __ldcs(&w4[2 * i]);
    float4 wb = __ldcs(&w4[2 * i + 1]);

    // 8 independent L2-hit gathers into the 2 MB g_gain table.
    float g0 = __ldg(&g_gain[sa.x]);
    float g1 = __ldg(&g_gain[sa.y]);
    float g2 = __ldg(&g_gain[sa.z]);
    float g3 = __ldg(&g_gain[sa.w]);
    float g4 = __ldg(&g_gain[sb.x]);
    float g5 = __ldg(&g_gain[sb.y]);
    float g6 = __ldg(&g_gain[sb.z]);
    float g7 = __ldg(&g_gain[sb.w]);

    // 8 no-return atomics (result unused -> RED.E.ADD.F32).
    atomicAdd(&out[da.x], wa.x * g0);
    atomicAdd(&out[da.y], wa.y * g1);
    atomicAdd(&out[da.z], wa.z * g2);
    atomicAdd(&out[da.w], wa.w * g3);
    atomicAdd(&out[db.x], wb.x * g4);
    atomicAdd(&out[db.y], wb.y * g5);
    atomicAdd(&out[db.z], wb.z * g6);
    atomicAdd(&out[db.w], wb.w * g7);
}

// ---------------------------------------------------------------------------
// Kernel C: out[n] = out[n] / tau[n]
// ---------------------------------------------------------------------------
__global__ void finalize(const float* __restrict__ tau,
                         float* __restrict__ out,
                         int n)
{
    int i = blockIdx.x * blockDim.x + threadIdx.x;
    if (i < n) {
        out[i] = out[i] / tau[i];
    }
}

// ---------------------------------------------------------------------------
// Launch
//   d_in: 0 voltage, 1 stimulus, 2 neuron_type(i32), 3 edge_index(i32 2xE),
//         4 w, 5 V_i_rest, 6 tau_i, 7 type_params
// ---------------------------------------------------------------------------
extern "C" void kernel_launch(void* const* d_in, const int* in_sizes, int n_in,
                              void* d_out, int out_size)
{
    const float* voltage = (const float*)d_in[0];
    const float* stim    = (const float*)d_in[1];
    const int*   ntype   = (const int*)d_in[2];
    const int*   eidx    = (const int*)d_in[3];
    const float* w       = (const float*)d_in[4];
    const float* vrest   = (const float*)d_in[5];
    const float* tau     = (const float*)d_in[6];
    const float* tparams = (const float*)d_in[7];
    float*       out     = (float*)d_out;

    const int n_nodes = N_NODES;
    const int n_edges = N_EDGES;

    // Kernel A
    {
        int threads = 256;
        int blocks = (n_nodes + threads - 1) / threads;
        node_prep<<<blocks, threads>>>(voltage, stim, ntype, vrest, tparams,
                                       out, n_nodes);
    }

    // Kernel B
    {
        const int4*   src4 = (const int4*)(eidx);
        const int4*   dst4 = (const int4*)(eidx + n_edges);
        const float4* w4   = (const float4*)w;
        int n_groups = n_edges / 8;           // 2,000,000 (exact)
        int threads = 256;
        int blocks = (n_groups + threads - 1) / threads;
        edge_scatter<<<blocks, threads>>>(src4, dst4, w4, out, n_groups);
    }

    // Kernel C
    {
        int threads = 256;
        int blocks = (n_nodes + threads - 1) / threads;
        finalize<<<blocks, threads>>>(tau, out, n_nodes);
    }
}

// round 5
// speedup vs baseline: 1.3829x; 1.3829x over previous
#include <cuda_runtime.h>
#include <cstdint>

#define N_NODES 500000
#define N_EDGES 16000000

// Per-node gain: relu(v[n]) * type_params[type[n]].  2 MB, stays L2-hot.
// ~50% of entries are exactly 0.0f (relu of N(0,1) voltage).
__device__ float g_gain[N_NODES];

// ---------------------------------------------------------------------------
// Kernel A: node prep. g_gain[n] = relu(v)*tp[type], out[n] = -v + stim + Vrest
// ---------------------------------------------------------------------------
__global__ void node_prep(const float* __restrict__ voltage,
                          const float* __restrict__ stimulus,
                          const int*   __restrict__ ntype,      // int32 (JAX x64 off)
                          const float* __restrict__ v_rest,
                          const float* __restrict__ type_params,
                          float* __restrict__ out,
                          int n)
{
    int i = blockIdx.x * blockDim.x + threadIdx.x;
    if (i < n) {
        float v = voltage[i];
        float r = v > 0.0f ? v : 0.0f;
        int t = ntype[i];                 // values in [0,64)
        g_gain[i] = r * __ldg(&type_params[t]);
        out[i] = -v + stimulus[i] + v_rest[i];
    }
}

// ---------------------------------------------------------------------------
// Kernel B: edge scatter. 4 edges per thread.
// Key optimization: ~50% of messages are exactly zero (relu-gated source).
// Adding 0.0f is a no-op, so predicate off the atomic -> ~half the REDG
// lanes. Spread-address RED cost is per-lane, so this halves atomic issue.
// ---------------------------------------------------------------------------
__global__ void __launch_bounds__(256) edge_scatter(
    const int4*   __restrict__ src4,   // edge_index row 0, int32 x4
    const int4*   __restrict__ dst4,   // edge_index row 1, int32 x4
    const float4* __restrict__ w4,
    float*        __restrict__ out,
    int n_groups)                      // N_EDGES / 4
{
    int i = blockIdx.x * blockDim.x + threadIdx.x;
    if (i >= n_groups) return;

    // streamed data: evict-first so it doesn't thrash L2-resident g_gain/out
    int4   s = __ldcs(&src4[i]);
    int4   d = __ldcs(&dst4[i]);
    float4 w = __ldcs(&w4[i]);

    float g0 = __ldg(&g_gain[s.x]);
    float g1 = __ldg(&g_gain[s.y]);
    float g2 = __ldg(&g_gain[s.z]);
    float g3 = __ldg(&g_gain[s.w]);

    float m0 = w.x * g0;
    float m1 = w.y * g1;
    float m2 = w.z * g2;
    float m3 = w.w * g3;

    // result unused -> RED.E.ADD.F32; predicated off when message is zero.
    if (m0 != 0.0f) atomicAdd(&out[d.x], m0);
    if (m1 != 0.0f) atomicAdd(&out[d.y], m1);
    if (m2 != 0.0f) atomicAdd(&out[d.z], m2);
    if (m3 != 0.0f) atomicAdd(&out[d.w], m3);
}

// ---------------------------------------------------------------------------
// Kernel C: out[n] = out[n] / tau[n]
// ---------------------------------------------------------------------------
__global__ void finalize(const float* __restrict__ tau,
                         float* __restrict__ out,
                         int n)
{
    int i = blockIdx.x * blockDim.x + threadIdx.x;
    if (i < n) {
        out[i] = out[i] / tau[i];
    }
}

// ---------------------------------------------------------------------------
// Launch
//   d_in: 0 voltage, 1 stimulus, 2 neuron_type(i32), 3 edge_index(i32 2xE),
//         4 w, 5 V_i_rest, 6 tau_i, 7 type_params
// ---------------------------------------------------------------------------
extern "C" void kernel_launch(void* const* d_in, const int* in_sizes, int n_in,
                              void* d_out, int out_size)
{
    const float* voltage = (const float*)d_in[0];
    const float* stim    = (const float*)d_in[1];
    const int*   ntype   = (const int*)d_in[2];
    const int*   eidx    = (const int*)d_in[3];
    const float* w       = (const float*)d_in[4];
    const float* vrest   = (const float*)d_in[5];
    const float* tau     = (const float*)d_in[6];
    const float* tparams = (const float*)d_in[7];
    float*       out     = (float*)d_out;

    const int n_nodes = N_NODES;
    const int n_edges = N_EDGES;

    // Kernel A
    {
        int threads = 256;
        int blocks = (n_nodes + threads - 1) / threads;
        node_prep<<<blocks, threads>>>(voltage, stim, ntype, vrest, tparams,
                                       out, n_nodes);
    }

    // Kernel B
    {
        const int4*   src4 = (const int4*)(eidx);
        const int4*   dst4 = (const int4*)(eidx + n_edges);
        const float4* w4   = (const float4*)w;
        int n_groups = n_edges / 4;           // 4,000,000 (exact)
        int threads = 256;
        int blocks = (n_groups + threads - 1) / threads;
        edge_scatter<<<blocks, threads>>>(src4, dst4, w4, out, n_groups);
    }

    // Kernel C
    {
        int threads = 256;
        int blocks = (n_nodes + threads - 1) / threads;
        finalize<<<blocks, threads>>>(tau, out, n_nodes);
    }
}